// round 2
// baseline (speedup 1.0000x reference)
#include <cuda_runtime.h>
#include <math.h>

#define NMAX 100000
#define EMAX 1600000

// ---------------- scratch (static device globals; no allocations) ----------
__device__ int   g_count[NMAX];
__device__ int   g_rowstart[NMAX + 1];
__device__ int   g_cursor[NMAX];
__device__ int   g_srcs[EMAX];
__device__ float g_invdeg[NMAX];
__device__ float g_agg[NMAX * 128];   // layer-1 mean aggregate
__device__ float g_h[NMAX * 128];     // hidden features
__device__ float g_agg2[NMAX * 128];  // layer-2 mean aggregate

// ---------------- f32x2 helpers (packed fp32 SIMD FMA) ---------------------
__device__ __forceinline__ unsigned long long bcast2(float a) {
    unsigned long long d;
    unsigned int r = __float_as_uint(a);
    asm("mov.b64 %0, {%1, %1};" : "=l"(d) : "r"(r));
    return d;
}
__device__ __forceinline__ unsigned long long fma2(unsigned long long a,
                                                   unsigned long long b,
                                                   unsigned long long c) {
    unsigned long long d;
    asm("fma.rn.f32x2 %0, %1, %2, %3;" : "=l"(d) : "l"(a), "l"(b), "l"(c));
    return d;
}
__device__ __forceinline__ float2 unpack2(unsigned long long v) {
    unsigned int lo, hi;
    asm("mov.b64 {%0, %1}, %2;" : "=r"(lo), "=r"(hi) : "l"(v));
    return make_float2(__uint_as_float(lo), __uint_as_float(hi));
}

// ---------------- CSR build -------------------------------------------------
__global__ void k_zero(int n) {
    int i = blockIdx.x * blockDim.x + threadIdx.x;
    if (i < n) g_count[i] = 0;
}

__global__ void k_hist(const int* __restrict__ dst, int e) {
    int i = blockIdx.x * blockDim.x + threadIdx.x;
    if (i < e) atomicAdd(&g_count[dst[i]], 1);
}

// single-block scan: 1024 threads, sequential chunks + Hillis-Steele over chunk sums
__global__ void k_scan(int n, int e) {
    __shared__ int ssum[1024];
    const int t = threadIdx.x;
    const int ch = (n + 1023) / 1024;
    int beg = t * ch;
    int end = beg + ch; if (end > n) end = n;
    int s = 0;
    for (int i = beg; i < end; i++) s += g_count[i];
    ssum[t] = s;
    __syncthreads();
    // inclusive scan
    for (int off = 1; off < 1024; off <<= 1) {
        int v = (t >= off) ? ssum[t - off] : 0;
        __syncthreads();
        ssum[t] += v;
        __syncthreads();
    }
    int prefix = ssum[t] - s;  // exclusive prefix for this chunk
    for (int i = beg; i < end; i++) {
        int c = g_count[i];
        g_rowstart[i] = prefix;
        g_cursor[i]   = prefix;
        g_invdeg[i]   = 1.0f / fmaxf((float)c, 1.0f);
        prefix += c;
    }
    if (t == 0) g_rowstart[n] = e;
}

__global__ void k_scatter(const int* __restrict__ src, const int* __restrict__ dst, int e) {
    int i = blockIdx.x * blockDim.x + threadIdx.x;
    if (i < e) {
        int pos = atomicAdd(&g_cursor[dst[i]], 1);
        g_srcs[pos] = src[i];
    }
}

// ---------------- mean aggregation: one warp per node -----------------------
__global__ void k_agg(const float4* __restrict__ xin, float4* __restrict__ outv, int n) {
    int node = blockIdx.x * (blockDim.x >> 5) + (threadIdx.x >> 5);
    if (node >= n) return;
    int lane = threadIdx.x & 31;
    int beg = g_rowstart[node];
    int end = g_rowstart[node + 1];
    float4 a0 = make_float4(0.f, 0.f, 0.f, 0.f);
    float4 a1 = make_float4(0.f, 0.f, 0.f, 0.f);
    int k = beg;
    for (; k + 1 < end; k += 2) {
        int s0 = __ldg(&g_srcs[k]);
        int s1 = __ldg(&g_srcs[k + 1]);
        float4 v0 = __ldg(&xin[s0 * 32 + lane]);
        float4 v1 = __ldg(&xin[s1 * 32 + lane]);
        a0.x += v0.x; a0.y += v0.y; a0.z += v0.z; a0.w += v0.w;
        a1.x += v1.x; a1.y += v1.y; a1.z += v1.z; a1.w += v1.w;
    }
    if (k < end) {
        int s0 = __ldg(&g_srcs[k]);
        float4 v0 = __ldg(&xin[s0 * 32 + lane]);
        a0.x += v0.x; a0.y += v0.y; a0.z += v0.z; a0.w += v0.w;
    }
    float inv = g_invdeg[node];
    float4 r = make_float4((a0.x + a1.x) * inv, (a0.y + a1.y) * inv,
                           (a0.z + a1.z) * inv, (a0.w + a1.w) * inv);
    outv[node * 32 + lane] = r;
}

// ---------------- layer 1: h = relu(agg@Wl1 + x@Wr1 + b1) -------------------
// block: 128 threads; tile 64 rows x 128 cols; thread micro-tile 8 rows x 8 cols
// K = 256 (agg 128 | x 128). W staged [256][128] in smem, A tile [64][260].
#define G1_SMEM ((256 * 128 + 64 * 260) * 4)
__global__ __launch_bounds__(128, 1)
void k_gemm1(const float* __restrict__ agg, const float* __restrict__ x,
             const float* __restrict__ Wl, const float* __restrict__ Wr,
             const float* __restrict__ bias, float* __restrict__ hout, int n)
{
    extern __shared__ float sm[];
    float* sW = sm;                // [256][128]
    float* sA = sm + 256 * 128;    // [64][260]
    const int tid = threadIdx.x;

    float4* sW4 = (float4*)sW;
    const float4* Wl4 = (const float4*)Wl;
    const float4* Wr4 = (const float4*)Wr;
    for (int i = tid; i < 4096; i += 128) sW4[i] = __ldg(&Wl4[i]);
    for (int i = tid; i < 4096; i += 128) sW4[4096 + i] = __ldg(&Wr4[i]);

    const int row0 = blockIdx.x * 64;
    const float4* agg4 = (const float4*)agg;
    const float4* x4   = (const float4*)x;
    for (int i = tid; i < 64 * 64; i += 128) {
        int r = i >> 6, q = i & 63;
        int gr = row0 + r;
        float4 v = make_float4(0.f, 0.f, 0.f, 0.f);
        if (gr < n) v = (q < 32) ? __ldg(&agg4[gr * 32 + q]) : __ldg(&x4[gr * 32 + q - 32]);
        *(float4*)&sA[r * 260 + q * 4] = v;
    }
    __syncthreads();

    const int tx = tid & 15, ty = tid >> 4;
    unsigned long long acc[8][4];
#pragma unroll
    for (int i = 0; i < 8; i++)
#pragma unroll
        for (int j = 0; j < 4; j++) acc[i][j] = 0ull;

    const ulonglong2* sW2 = (const ulonglong2*)sW;
    const float* sa = &sA[ty * 8 * 260];
#pragma unroll 2
    for (int k = 0; k < 256; k++) {
        ulonglong2 wA = sW2[k * 32 + tx];
        ulonglong2 wB = sW2[k * 32 + 16 + tx];
#pragma unroll
        for (int i = 0; i < 8; i++) {
            unsigned long long aa = bcast2(sa[i * 260 + k]);
            acc[i][0] = fma2(aa, wA.x, acc[i][0]);
            acc[i][1] = fma2(aa, wA.y, acc[i][1]);
            acc[i][2] = fma2(aa, wB.x, acc[i][2]);
            acc[i][3] = fma2(aa, wB.y, acc[i][3]);
        }
    }

    const float4* b4 = (const float4*)bias;
    float4 bv0 = __ldg(&b4[tx]);
    float4 bv1 = __ldg(&b4[16 + tx]);
    float4* h4 = (float4*)hout;
#pragma unroll
    for (int i = 0; i < 8; i++) {
        int gr = row0 + ty * 8 + i;
        if (gr >= n) break;
        float2 p0 = unpack2(acc[i][0]), p1 = unpack2(acc[i][1]);
        float2 p2 = unpack2(acc[i][2]), p3 = unpack2(acc[i][3]);
        float4 o0 = make_float4(fmaxf(p0.x + bv0.x, 0.f), fmaxf(p0.y + bv0.y, 0.f),
                                fmaxf(p1.x + bv0.z, 0.f), fmaxf(p1.y + bv0.w, 0.f));
        float4 o1 = make_float4(fmaxf(p2.x + bv1.x, 0.f), fmaxf(p2.y + bv1.y, 0.f),
                                fmaxf(p3.x + bv1.z, 0.f), fmaxf(p3.y + bv1.w, 0.f));
        h4[gr * 32 + tx]      = o0;
        h4[gr * 32 + 16 + tx] = o1;
    }
}

// ---------------- layer 2 + log_softmax -------------------------------------
// block: 128 threads; tile 64 rows x 64 cols (full NCLS); K = 256 (agg2|h).
#define G2_SMEM ((256 * 64 + 64 * 260) * 4)
__global__ __launch_bounds__(128, 1)
void k_gemm2(const float* __restrict__ agg, const float* __restrict__ h,
             const float* __restrict__ Wl, const float* __restrict__ Wr,
             const float* __restrict__ bias, float* __restrict__ out, int n)
{
    extern __shared__ float sm[];
    float* sW = sm;               // [256][64]
    float* sA = sm + 256 * 64;    // [64][260], reused as sOut[64][69]
    __shared__ float slse[64];
    const int tid = threadIdx.x;

    float4* sW4 = (float4*)sW;
    const float4* Wl4 = (const float4*)Wl;
    const float4* Wr4 = (const float4*)Wr;
    for (int i = tid; i < 2048; i += 128) sW4[i] = __ldg(&Wl4[i]);
    for (int i = tid; i < 2048; i += 128) sW4[2048 + i] = __ldg(&Wr4[i]);

    const int row0 = blockIdx.x * 64;
    const float4* a4 = (const float4*)agg;
    const float4* h4 = (const float4*)h;
    for (int i = tid; i < 64 * 64; i += 128) {
        int r = i >> 6, q = i & 63;
        int gr = row0 + r;
        float4 v = make_float4(0.f, 0.f, 0.f, 0.f);
        if (gr < n) v = (q < 32) ? __ldg(&a4[gr * 32 + q]) : __ldg(&h4[gr * 32 + q - 32]);
        *(float4*)&sA[r * 260 + q * 4] = v;
    }
    __syncthreads();

    const int tx = tid & 15, ty = tid >> 4;
    unsigned long long acc[8][2];
#pragma unroll
    for (int i = 0; i < 8; i++) { acc[i][0] = 0ull; acc[i][1] = 0ull; }

    const ulonglong2* sW2 = (const ulonglong2*)sW;
    const float* sa = &sA[ty * 8 * 260];
#pragma unroll 2
    for (int k = 0; k < 256; k++) {
        ulonglong2 w = sW2[k * 16 + tx];
#pragma unroll
        for (int i = 0; i < 8; i++) {
            unsigned long long aa = bcast2(sa[i * 260 + k]);
            acc[i][0] = fma2(aa, w.x, acc[i][0]);
            acc[i][1] = fma2(aa, w.y, acc[i][1]);
        }
    }

    float4 bv = __ldg(&((const float4*)bias)[tx]);
    __syncthreads();  // everyone done reading sA
    float* sO = sA;   // [64][69]
#pragma unroll
    for (int i = 0; i < 8; i++) {
        int r = ty * 8 + i;
        float2 p0 = unpack2(acc[i][0]), p1 = unpack2(acc[i][1]);
        sO[r * 69 + tx * 4 + 0] = p0.x + bv.x;
        sO[r * 69 + tx * 4 + 1] = p0.y + bv.y;
        sO[r * 69 + tx * 4 + 2] = p1.x + bv.z;
        sO[r * 69 + tx * 4 + 3] = p1.y + bv.w;
    }
    __syncthreads();

    if (tid < 64) {
        int r = tid;
        const float* row = &sO[r * 69];
        float m = -3.4e38f;
        for (int j = 0; j < 64; j++) m = fmaxf(m, row[j]);
        float s = 0.f;
        for (int j = 0; j < 64; j++) s += expf(row[j] - m);
        slse[r] = m + logf(s);
    }
    __syncthreads();

    // coalesced write of log_softmax result
    float4* out4 = (float4*)out;
    for (int i = tid; i < 64 * 16; i += 128) {
        int r = i >> 4, q = i & 15;
        int gr = row0 + r;
        if (gr < n) {
            float l = slse[r];
            const float* row = &sO[r * 69];
            float4 o = make_float4(row[q * 4 + 0] - l, row[q * 4 + 1] - l,
                                   row[q * 4 + 2] - l, row[q * 4 + 3] - l);
            out4[gr * 16 + q] = o;
        }
    }
}

// ---------------- launch -----------------------------------------------------
extern "C" void kernel_launch(void* const* d_in, const int* in_sizes, int n_in,
                              void* d_out, int out_size)
{
    const float* x   = (const float*)d_in[0];
    const int*   ei  = (const int*)d_in[1];
    const float* Wl1 = (const float*)d_in[2];
    const float* Wr1 = (const float*)d_in[3];
    const float* b1  = (const float*)d_in[4];
    const float* Wl2 = (const float*)d_in[5];
    const float* Wr2 = (const float*)d_in[6];
    const float* b2  = (const float*)d_in[7];
    float* out = (float*)d_out;

    const int n = in_sizes[0] / 128;
    const int e = in_sizes[1] / 2;
    const int* src = ei;
    const int* dst = ei + e;

    cudaFuncSetAttribute(k_gemm1, cudaFuncAttributeMaxDynamicSharedMemorySize, G1_SMEM);
    cudaFuncSetAttribute(k_gemm2, cudaFuncAttributeMaxDynamicSharedMemorySize, G2_SMEM);

    void *p_agg = nullptr, *p_h = nullptr, *p_agg2 = nullptr;
    cudaGetSymbolAddress(&p_agg,  g_agg);
    cudaGetSymbolAddress(&p_h,    g_h);
    cudaGetSymbolAddress(&p_agg2, g_agg2);
    float* agg  = (float*)p_agg;
    float* hbuf = (float*)p_h;
    float* agg2 = (float*)p_agg2;

    k_zero<<<(n + 255) / 256, 256>>>(n);
    k_hist<<<(e + 255) / 256, 256>>>(dst, e);
    k_scan<<<1, 1024>>>(n, e);
    k_scatter<<<(e + 255) / 256, 256>>>(src, dst, e);

    // layer 1
    k_agg<<<(n + 7) / 8, 256>>>((const float4*)x, (float4*)agg, n);
    k_gemm1<<<(n + 63) / 64, 128, G1_SMEM>>>(agg, x, Wl1, Wr1, b1, hbuf, n);

    // layer 2
    k_agg<<<(n + 7) / 8, 256>>>((const float4*)hbuf, (float4*)agg2, n);
    k_gemm2<<<(n + 63) / 64, 128, G2_SMEM>>>(agg2, hbuf, Wl2, Wr2, b2, out, n);
}

// round 3
// speedup vs baseline: 2.0864x; 2.0864x over previous
#include <cuda_runtime.h>
#include <math.h>

#define NMAX 100000
#define EMAX 1600000
#define FULL 0xffffffffu

// ---------------- scratch (static device globals; no allocations) ----------
__device__ int   g_count[NMAX];
__device__ int   g_rowstart[NMAX + 1];
__device__ int   g_cursor[NMAX];
__device__ int   g_srcs[EMAX];
__device__ float g_invdeg[NMAX];
__device__ int   g_bsum[64];
__device__ int   g_bbase[64];
__device__ float g_agg[NMAX * 128];   // layer-1 aggregate; later: z | agg2(z)
__device__ float g_h[NMAX * 128];     // hidden features
__device__ float g_pre[NMAX * 64];    // h@Wr2 + b2

// ---------------- f32x2 helpers (packed fp32 SIMD FMA) ---------------------
__device__ __forceinline__ unsigned long long bcast2(float a) {
    unsigned long long d;
    unsigned int r = __float_as_uint(a);
    asm("mov.b64 %0, {%1, %1};" : "=l"(d) : "r"(r));
    return d;
}
__device__ __forceinline__ unsigned long long fma2(unsigned long long a,
                                                   unsigned long long b,
                                                   unsigned long long c) {
    unsigned long long d;
    asm("fma.rn.f32x2 %0, %1, %2, %3;" : "=l"(d) : "l"(a), "l"(b), "l"(c));
    return d;
}
__device__ __forceinline__ float2 unpack2(unsigned long long v) {
    unsigned int lo, hi;
    asm("mov.b64 {%0, %1}, %2;" : "=r"(lo), "=r"(hi) : "l"(v));
    return make_float2(__uint_as_float(lo), __uint_as_float(hi));
}

// ---------------- CSR build -------------------------------------------------
__global__ void k_zero(int n) {
    int i = blockIdx.x * blockDim.x + threadIdx.x;
    if (i < n) g_count[i] = 0;
}

__global__ void k_hist(const int* __restrict__ dst, int e) {
    int i = blockIdx.x * blockDim.x + threadIdx.x;
    if (i < e) atomicAdd(&g_count[dst[i]], 1);
}

// phase 1: per-block (2048 counts) sums
__global__ void k_bsum(int n) {
    const int tid = threadIdx.x;
    const int gbase = blockIdx.x * 2048 + tid * 4;
    int s = 0;
#pragma unroll
    for (int j = 0; j < 4; j++)
        if (gbase + j < n) s += g_count[gbase + j];
    const int lane = tid & 31, wid = tid >> 5;
#pragma unroll
    for (int off = 16; off > 0; off >>= 1) s += __shfl_down_sync(FULL, s, off);
    __shared__ int w[16];
    if (lane == 0) w[wid] = s;
    __syncthreads();
    if (tid == 0) {
        int t = 0;
#pragma unroll
        for (int i = 0; i < 16; i++) t += w[i];
        g_bsum[blockIdx.x] = t;
    }
}

// phase 2: scan block sums (B <= 64), also write rowstart[n]
__global__ void k_bscan(int B, int n, int e) {
    __shared__ int s[64];
    const int t = threadIdx.x;
    int v = (t < B) ? g_bsum[t] : 0;
    s[t] = v;
    __syncthreads();
    for (int off = 1; off < 64; off <<= 1) {
        int u = (t >= off) ? s[t - off] : 0;
        __syncthreads();
        s[t] += u;
        __syncthreads();
    }
    if (t < B) g_bbase[t] = s[t] - v;  // exclusive prefix
    if (t == 0) g_rowstart[n] = e;
}

// phase 3: fill rowstart/cursor/invdeg
__global__ void k_fill(int n) {
    const int tid = threadIdx.x;
    const int lane = tid & 31, wid = tid >> 5;
    const int gbase = blockIdx.x * 2048 + tid * 4;
    int c[4];
    int s = 0;
#pragma unroll
    for (int j = 0; j < 4; j++) {
        c[j] = (gbase + j < n) ? g_count[gbase + j] : 0;
        s += c[j];
    }
    int incl = s;
#pragma unroll
    for (int off = 1; off < 32; off <<= 1) {
        int u = __shfl_up_sync(FULL, incl, off);
        if (lane >= off) incl += u;
    }
    __shared__ int wsum[16];
    if (lane == 31) wsum[wid] = incl;
    __syncthreads();
    if (tid < 16) {
        int v = wsum[tid];
#pragma unroll
        for (int off = 1; off < 16; off <<= 1) {
            int u = __shfl_up_sync(0xffffu, v, off);
            if (tid >= off) v += u;
        }
        wsum[tid] = v;
    }
    __syncthreads();
    int base = g_bbase[blockIdx.x] + (incl - s) + (wid ? wsum[wid - 1] : 0);
#pragma unroll
    for (int j = 0; j < 4; j++) {
        if (gbase + j < n) {
            g_rowstart[gbase + j] = base;
            g_cursor[gbase + j] = base;
            g_invdeg[gbase + j] = 1.0f / fmaxf((float)c[j], 1.0f);
            base += c[j];
        }
    }
}

__global__ void k_scatter(const int* __restrict__ src, const int* __restrict__ dst, int e) {
    int i = blockIdx.x * blockDim.x + threadIdx.x;
    if (i < e) {
        int pos = atomicAdd(&g_cursor[dst[i]], 1);
        g_srcs[pos] = src[i];
    }
}

// ---------------- 128-dim mean aggregation: warp per node, shfl idx --------
__global__ void k_agg128(const float4* __restrict__ xin, float4* __restrict__ outv, int n) {
    int node = blockIdx.x * (blockDim.x >> 5) + (threadIdx.x >> 5);
    if (node >= n) return;
    const int lane = threadIdx.x & 31;
    const int beg = g_rowstart[node];
    const int cnt = g_rowstart[node + 1] - beg;

    float4 a0 = make_float4(0.f, 0.f, 0.f, 0.f);
    float4 a1 = make_float4(0.f, 0.f, 0.f, 0.f);
    float4 a2 = make_float4(0.f, 0.f, 0.f, 0.f);
    float4 a3 = make_float4(0.f, 0.f, 0.f, 0.f);

    for (int base = 0; base < cnt; base += 32) {
        const int m = min(32, cnt - base);
        int idx = (lane < m) ? __ldg(&g_srcs[beg + base + lane]) : 0;
        int j = 0;
        for (; j + 3 < m; j += 4) {
            int s0 = __shfl_sync(FULL, idx, j);
            int s1 = __shfl_sync(FULL, idx, j + 1);
            int s2 = __shfl_sync(FULL, idx, j + 2);
            int s3 = __shfl_sync(FULL, idx, j + 3);
            float4 v0 = __ldg(&xin[s0 * 32 + lane]);
            float4 v1 = __ldg(&xin[s1 * 32 + lane]);
            float4 v2 = __ldg(&xin[s2 * 32 + lane]);
            float4 v3 = __ldg(&xin[s3 * 32 + lane]);
            a0.x += v0.x; a0.y += v0.y; a0.z += v0.z; a0.w += v0.w;
            a1.x += v1.x; a1.y += v1.y; a1.z += v1.z; a1.w += v1.w;
            a2.x += v2.x; a2.y += v2.y; a2.z += v2.z; a2.w += v2.w;
            a3.x += v3.x; a3.y += v3.y; a3.z += v3.z; a3.w += v3.w;
        }
        for (; j < m; j++) {
            int s0 = __shfl_sync(FULL, idx, j);
            float4 v0 = __ldg(&xin[s0 * 32 + lane]);
            a0.x += v0.x; a0.y += v0.y; a0.z += v0.z; a0.w += v0.w;
        }
    }
    const float inv = g_invdeg[node];
    float4 r = make_float4((a0.x + a1.x + a2.x + a3.x) * inv,
                           (a0.y + a1.y + a2.y + a3.y) * inv,
                           (a0.z + a1.z + a2.z + a3.z) * inv,
                           (a0.w + a1.w + a2.w + a3.w) * inv);
    outv[node * 32 + lane] = r;
}

// ---------------- 64-dim mean aggregation: half-warp per node --------------
__global__ void k_agg64(const float4* __restrict__ zin, float4* __restrict__ outv, int n) {
    const int warp = blockIdx.x * (blockDim.x >> 5) + (threadIdx.x >> 5);
    const int lane = threadIdx.x & 31;
    const int half = lane >> 4, hl = lane & 15;
    const int node = warp * 2 + half;
    const bool valid = node < n;
    int beg = 0, cnt = 0;
    if (valid) {
        beg = g_rowstart[node];
        cnt = g_rowstart[node + 1] - beg;
    }
    int mx = cnt;
#pragma unroll
    for (int off = 16; off > 0; off >>= 1) mx = max(mx, __shfl_xor_sync(FULL, mx, off));

    float4 a0 = make_float4(0.f, 0.f, 0.f, 0.f);
    float4 a1 = make_float4(0.f, 0.f, 0.f, 0.f);
    for (int base = 0; base < mx; base += 16) {
        int idx = 0;
        if (base + hl < cnt) idx = __ldg(&g_srcs[beg + base + hl]);
        const int m = cnt - base;  // may be <=0 for the short half
#pragma unroll 4
        for (int j = 0; j < 16; j += 2) {
            int s0 = __shfl_sync(FULL, idx, half * 16 + j);
            int s1 = __shfl_sync(FULL, idx, half * 16 + j + 1);
            if (j < m) {
                float4 v = __ldg(&zin[s0 * 16 + hl]);
                a0.x += v.x; a0.y += v.y; a0.z += v.z; a0.w += v.w;
            }
            if (j + 1 < m) {
                float4 v = __ldg(&zin[s1 * 16 + hl]);
                a1.x += v.x; a1.y += v.y; a1.z += v.z; a1.w += v.w;
            }
        }
    }
    if (valid) {
        const float inv = g_invdeg[node];
        float4 r = make_float4((a0.x + a1.x) * inv, (a0.y + a1.y) * inv,
                               (a0.z + a1.z) * inv, (a0.w + a1.w) * inv);
        outv[node * 16 + hl] = r;
    }
}

// ---------------- layer 1: h = relu(agg@Wl1 + x@Wr1 + b1) -------------------
// 256 threads; tile 128 rows x 128 cols; K chunked 2x128; micro 8x8/thread.
#define G_SMEM ((128 * 128 + 128 * 132) * 4)
__global__ __launch_bounds__(256, 1)
void k_gemm1(const float* __restrict__ agg, const float* __restrict__ x,
             const float* __restrict__ Wl, const float* __restrict__ Wr,
             const float* __restrict__ bias, float* __restrict__ hout, int n)
{
    extern __shared__ float sm[];
    float* sW = sm;                // [128][128]
    float* sA = sm + 128 * 128;    // [128][132]
    const int tid = threadIdx.x;
    const int row0 = blockIdx.x * 128;
    const int tx = tid & 15, ty = tid >> 4;

    unsigned long long acc[8][4];
#pragma unroll
    for (int i = 0; i < 8; i++)
#pragma unroll
        for (int j = 0; j < 4; j++) acc[i][j] = 0ull;

    float4* sW4 = (float4*)sW;
#pragma unroll 1
    for (int chunk = 0; chunk < 2; chunk++) {
        const float4* Wsrc = (const float4*)(chunk ? Wr : Wl);
        const float4* Asrc = (const float4*)(chunk ? x : agg);
        for (int i = tid; i < 4096; i += 256) sW4[i] = __ldg(&Wsrc[i]);
        for (int i = tid; i < 4096; i += 256) {
            int r = i >> 5, q = i & 31;
            int gr = row0 + r;
            float4 v = make_float4(0.f, 0.f, 0.f, 0.f);
            if (gr < n) v = __ldg(&Asrc[gr * 32 + q]);
            *(float4*)&sA[r * 132 + q * 4] = v;
        }
        __syncthreads();

        const ulonglong2* sW2 = (const ulonglong2*)sW;
        const float* sa = &sA[ty * 8 * 132];
#pragma unroll 2
        for (int k = 0; k < 128; k++) {
            ulonglong2 wA = sW2[k * 32 + tx];
            ulonglong2 wB = sW2[k * 32 + 16 + tx];
#pragma unroll
            for (int i = 0; i < 8; i++) {
                unsigned long long aa = bcast2(sa[i * 132 + k]);
                acc[i][0] = fma2(aa, wA.x, acc[i][0]);
                acc[i][1] = fma2(aa, wA.y, acc[i][1]);
                acc[i][2] = fma2(aa, wB.x, acc[i][2]);
                acc[i][3] = fma2(aa, wB.y, acc[i][3]);
            }
        }
        __syncthreads();
    }

    const float4* b4 = (const float4*)bias;
    float4 bv0 = __ldg(&b4[tx]);
    float4 bv1 = __ldg(&b4[16 + tx]);
    float4* h4 = (float4*)hout;
#pragma unroll
    for (int i = 0; i < 8; i++) {
        int gr = row0 + ty * 8 + i;
        if (gr >= n) break;
        float2 p0 = unpack2(acc[i][0]), p1 = unpack2(acc[i][1]);
        float2 p2 = unpack2(acc[i][2]), p3 = unpack2(acc[i][3]);
        float4 o0 = make_float4(fmaxf(p0.x + bv0.x, 0.f), fmaxf(p0.y + bv0.y, 0.f),
                                fmaxf(p1.x + bv0.z, 0.f), fmaxf(p1.y + bv0.w, 0.f));
        float4 o1 = make_float4(fmaxf(p2.x + bv1.x, 0.f), fmaxf(p2.y + bv1.y, 0.f),
                                fmaxf(p3.x + bv1.z, 0.f), fmaxf(p3.y + bv1.w, 0.f));
        h4[gr * 32 + tx]      = o0;
        h4[gr * 32 + 16 + tx] = o1;
    }
}

// ---------------- layer 2 projections: [z | pre] = h @ [Wl2 | Wr2] ----------
// z = h@Wl2 (no bias, aggregated later); pre = h@Wr2 + b2. K=128, 128 cols.
__global__ __launch_bounds__(256, 1)
void k_gemmzp(const float* __restrict__ h,
              const float* __restrict__ Wl, const float* __restrict__ Wr,
              const float* __restrict__ bias,
              float* __restrict__ z, float* __restrict__ pre, int n)
{
    extern __shared__ float sm[];
    float* sW = sm;                // [128][128] = [Wl2 | Wr2]
    float* sA = sm + 128 * 128;    // [128][132]
    const int tid = threadIdx.x;
    const int row0 = blockIdx.x * 128;
    const int tx = tid & 15, ty = tid >> 4;

    float4* sW4 = (float4*)sW;
    const float4* Wl4 = (const float4*)Wl;
    const float4* Wr4 = (const float4*)Wr;
    for (int i = tid; i < 4096; i += 256) {
        int k = i >> 5, q = i & 31;
        float4 v = (q < 16) ? __ldg(&Wl4[k * 16 + q]) : __ldg(&Wr4[k * 16 + (q - 16)]);
        sW4[i] = v;
    }
    const float4* h4 = (const float4*)h;
    for (int i = tid; i < 4096; i += 256) {
        int r = i >> 5, q = i & 31;
        int gr = row0 + r;
        float4 v = make_float4(0.f, 0.f, 0.f, 0.f);
        if (gr < n) v = __ldg(&h4[gr * 32 + q]);
        *(float4*)&sA[r * 132 + q * 4] = v;
    }
    __syncthreads();

    unsigned long long acc[8][4];
#pragma unroll
    for (int i = 0; i < 8; i++)
#pragma unroll
        for (int j = 0; j < 4; j++) acc[i][j] = 0ull;

    const ulonglong2* sW2 = (const ulonglong2*)sW;
    const float* sa = &sA[ty * 8 * 132];
#pragma unroll 2
    for (int k = 0; k < 128; k++) {
        ulonglong2 wA = sW2[k * 32 + tx];
        ulonglong2 wB = sW2[k * 32 + 16 + tx];
#pragma unroll
        for (int i = 0; i < 8; i++) {
            unsigned long long aa = bcast2(sa[i * 132 + k]);
            acc[i][0] = fma2(aa, wA.x, acc[i][0]);
            acc[i][1] = fma2(aa, wA.y, acc[i][1]);
            acc[i][2] = fma2(aa, wB.x, acc[i][2]);
            acc[i][3] = fma2(aa, wB.y, acc[i][3]);
        }
    }

    float4 bv = __ldg(&((const float4*)bias)[tx]);
    float4* z4 = (float4*)z;
    float4* p4 = (float4*)pre;
#pragma unroll
    for (int i = 0; i < 8; i++) {
        int gr = row0 + ty * 8 + i;
        if (gr >= n) break;
        float2 p0 = unpack2(acc[i][0]), p1 = unpack2(acc[i][1]);
        float2 p2 = unpack2(acc[i][2]), p3 = unpack2(acc[i][3]);
        z4[gr * 16 + tx] = make_float4(p0.x, p0.y, p1.x, p1.y);
        p4[gr * 16 + tx] = make_float4(p2.x + bv.x, p2.y + bv.y,
                                       p3.x + bv.z, p3.y + bv.w);
    }
}

// ---------------- epilogue: out = log_softmax(pre + agg2) -------------------
__global__ void k_out(const float2* __restrict__ pre2, const float2* __restrict__ ag2,
                      float2* __restrict__ out2, int n)
{
    const int row = blockIdx.x * (blockDim.x >> 5) + (threadIdx.x >> 5);
    if (row >= n) return;
    const int lane = threadIdx.x & 31;
    float2 p = __ldg(&pre2[row * 32 + lane]);
    float2 a = __ldg(&ag2[row * 32 + lane]);
    float2 v = make_float2(p.x + a.x, p.y + a.y);
    float m = fmaxf(v.x, v.y);
#pragma unroll
    for (int off = 16; off > 0; off >>= 1) m = fmaxf(m, __shfl_xor_sync(FULL, m, off));
    float s = expf(v.x - m) + expf(v.y - m);
#pragma unroll
    for (int off = 16; off > 0; off >>= 1) s += __shfl_xor_sync(FULL, s, off);
    float lse = m + logf(s);
    out2[row * 32 + lane] = make_float2(v.x - lse, v.y - lse);
}

// ---------------- launch -----------------------------------------------------
extern "C" void kernel_launch(void* const* d_in, const int* in_sizes, int n_in,
                              void* d_out, int out_size)
{
    const float* x   = (const float*)d_in[0];
    const int*   ei  = (const int*)d_in[1];
    const float* Wl1 = (const float*)d_in[2];
    const float* Wr1 = (const float*)d_in[3];
    const float* b1  = (const float*)d_in[4];
    const float* Wl2 = (const float*)d_in[5];
    const float* Wr2 = (const float*)d_in[6];
    const float* b2  = (const float*)d_in[7];
    float* out = (float*)d_out;

    const int n = in_sizes[0] / 128;
    const int e = in_sizes[1] / 2;
    const int* src = ei;
    const int* dst = ei + e;

    cudaFuncSetAttribute(k_gemm1,  cudaFuncAttributeMaxDynamicSharedMemorySize, G_SMEM);
    cudaFuncSetAttribute(k_gemmzp, cudaFuncAttributeMaxDynamicSharedMemorySize, G_SMEM);

    void *p_agg = nullptr, *p_h = nullptr, *p_pre = nullptr;
    cudaGetSymbolAddress(&p_agg, g_agg);
    cudaGetSymbolAddress(&p_h,   g_h);
    cudaGetSymbolAddress(&p_pre, g_pre);
    float* agg  = (float*)p_agg;                 // [N,128] layer-1 aggregate
    float* zbuf = (float*)p_agg;                 // reuse: z = h@Wl2 [N,64]
    float* a2   = (float*)p_agg + (size_t)NMAX * 64;  // agg2(z) [N,64]
    float* hbuf = (float*)p_h;
    float* pre  = (float*)p_pre;

    const int B = (n + 2047) / 2048;

    // CSR build
    k_zero<<<(n + 1023) / 1024, 1024>>>(n);
    k_hist<<<(e + 255) / 256, 256>>>(dst, e);
    k_bsum<<<B, 512>>>(n);
    k_bscan<<<1, 64>>>(B, n, e);
    k_fill<<<B, 512>>>(n);
    k_scatter<<<(e + 255) / 256, 256>>>(src, dst, e);

    // layer 1
    k_agg128<<<(n + 7) / 8, 256>>>((const float4*)x, (float4*)agg, n);
    k_gemm1<<<(n + 127) / 128, 256, G_SMEM>>>(agg, x, Wl1, Wr1, b1, hbuf, n);

    // layer 2 (projection first: agg commutes with the linear map)
    k_gemmzp<<<(n + 127) / 128, 256, G_SMEM>>>(hbuf, Wl2, Wr2, b2, zbuf, pre, n);
    k_agg64<<<(n + 15) / 16, 256>>>((const float4*)zbuf, (float4*)a2, n);
    k_out<<<(n + 7) / 8, 256>>>((const float2*)pre, (const float2*)a2, (float2*)out, n);
}